// round 2
// baseline (speedup 1.0000x reference)
#include <cuda_runtime.h>
#include <cstdint>
#include <cstddef>

// ---------------- problem constants ----------------
constexpr int B_SZ  = 8192;
constexpr int IN_SZ = 2048;
constexpr int H_SZ  = 2048;
constexpr int K_SZ  = IN_SZ + H_SZ;       // 4096
constexpr int N_SZ  = 4 * H_SZ;           // 8192 (f,i,g,o stacked)

// GEMM tiling
constexpr int BM = 128, BN = 128, BK = 32;
constexpr int STAGES = 3;
constexpr int KT = K_SZ / BK;             // 128 k-tiles
constexpr int LDSP = 36;                  // padded floats per smem row (bank-conflict-free)
constexpr int TILE_F = 128 * LDSP;        // floats per operand tile in smem
constexpr int SMEM_BYTES = 2 * STAGES * TILE_F * 4;   // 110592 B

// scratch for gates [B, 4H] fp32  (static device array: allowed scratch path)
__device__ float g_gates[(size_t)B_SZ * N_SZ];

#define DEVI __device__ __forceinline__

DEVI uint32_t smem_u32(const void* p) {
    uint32_t a;
    asm("{ .reg .u64 t; cvta.to.shared.u64 t, %1; cvt.u32.u64 %0, t; }"
        : "=r"(a) : "l"(p));
    return a;
}

DEVI void cp_async16(uint32_t dst, const void* src) {
    asm volatile("cp.async.cg.shared.global [%0], [%1], 16;"
                 :: "r"(dst), "l"(src) : "memory");
}
DEVI void cp_commit() { asm volatile("cp.async.commit_group;" ::: "memory"); }
template <int N> DEVI void cp_wait() {
    asm volatile("cp.async.wait_group %0;" :: "n"(N) : "memory");
}

DEVI uint32_t to_tf32(float x) {
    uint32_t u;
    asm("cvt.rna.tf32.f32 %0, %1;" : "=r"(u) : "f"(x));
    return u;
}

DEVI void mma_tf32(float c[4], const uint32_t a[4], const uint32_t b[2]) {
    asm volatile(
        "mma.sync.aligned.m16n8k8.row.col.f32.tf32.tf32.f32 "
        "{%0,%1,%2,%3},{%4,%5,%6,%7},{%8,%9},{%0,%1,%2,%3};"
        : "+f"(c[0]), "+f"(c[1]), "+f"(c[2]), "+f"(c[3])
        : "r"(a[0]), "r"(a[1]), "r"(a[2]), "r"(a[3]), "r"(b[0]), "r"(b[1]));
}

// ---------------- kernel 1: fused 4-gate GEMM (no bias) ----------------
// gates[m, n] = sum_k combined[m, k] * W_all[n, k]
// combined = [input | h_prev] along k; W_all rows: gate = n / 2048.
__global__ void __launch_bounds__(256, 1)
gemm_gates_kernel(const float* __restrict__ inp,  // [B, 2048]
                  const float* __restrict__ hpv,  // [B, 2048]
                  const float* __restrict__ Wf, const float* __restrict__ Wi,
                  const float* __restrict__ Wg, const float* __restrict__ Wo)
{
    extern __shared__ float sm[];
    float* smA = sm;                       // [STAGES][128][36]
    float* smB = sm + STAGES * TILE_F;

    const int tid  = threadIdx.x;
    const int lane = tid & 31;
    const int warp = tid >> 5;
    const int wm   = warp >> 2;            // 0..1  (M)
    const int wn   = warp & 3;             // 0..3  (N)

    // grid swizzle: 8 m-tiles per group for L2 reuse
    constexpr int NT = N_SZ / BN;           // 64
    constexpr int GM = 8;
    const int bid   = blockIdx.x;
    const int group = bid / (GM * NT);
    const int rem   = bid % (GM * NT);
    const int mt    = group * GM + (rem % GM);
    const int nt    = rem / GM;

    const int m0 = mt * BM;
    const int n0 = nt * BN;                 // global column in [0, 8192)
    const int gate = nt >> 4;               // 2048/128 = 16 n-tiles per gate
    const float* W = (gate == 0) ? Wf : (gate == 1) ? Wi : (gate == 2) ? Wg : Wo;
    const int nw0 = (nt & 15) * BN;         // row offset within this gate's W [2048, 4096]

    const uint32_t smA_u = smem_u32(smA);
    const uint32_t smB_u = smem_u32(smB);

    // ---- stage loader: 4 float4 per thread per operand ----
    auto load_stage = [&](int kt, int st) {
        const int kb = kt * BK;
        const float* Asrc = (kb < IN_SZ) ? (inp + kb) : (hpv + (kb - IN_SZ));
        const uint32_t adst = smA_u + st * TILE_F * 4;
        const uint32_t bdst = smB_u + st * TILE_F * 4;
        #pragma unroll
        for (int i = 0; i < 4; ++i) {
            const int lin = tid + i * 256;          // 0..1023
            const int row = lin >> 3;               // 0..127
            const int c4  = (lin & 7) * 4;          // 0,4,...,28
            cp_async16(adst + (row * LDSP + c4) * 4,
                       Asrc + (size_t)(m0 + row) * 2048 + c4);
            cp_async16(bdst + (row * LDSP + c4) * 4,
                       W + (size_t)(nw0 + row) * K_SZ + kb + c4);
        }
    };

    float acc[4][4][4];
    #pragma unroll
    for (int a = 0; a < 4; ++a)
        #pragma unroll
        for (int b = 0; b < 4; ++b)
            #pragma unroll
            for (int c = 0; c < 4; ++c) acc[a][b][c] = 0.f;

    // prologue
    load_stage(0, 0); cp_commit();
    load_stage(1, 1); cp_commit();

    int rs = 0;
    for (int kt = 0; kt < KT; ++kt) {
        cp_wait<STAGES - 2>();
        __syncthreads();

        if (kt + STAGES - 1 < KT) load_stage(kt + STAGES - 1, (kt + STAGES - 1) % STAGES);
        cp_commit();

        const float* As = smA + rs * TILE_F;
        const float* Bs = smB + rs * TILE_F;

        #pragma unroll
        for (int ks = 0; ks < 4; ++ks) {
            const int col = ks * 8 + (lane & 3);
            uint32_t af[4][4], bf2[4][2];
            #pragma unroll
            for (int mi = 0; mi < 4; ++mi) {
                const int r = wm * 64 + mi * 16 + (lane >> 2);
                af[mi][0] = to_tf32(As[r * LDSP + col]);
                af[mi][1] = to_tf32(As[(r + 8) * LDSP + col]);
                af[mi][2] = to_tf32(As[r * LDSP + col + 4]);
                af[mi][3] = to_tf32(As[(r + 8) * LDSP + col + 4]);
            }
            #pragma unroll
            for (int ni = 0; ni < 4; ++ni) {
                const int r = wn * 32 + ni * 8 + (lane >> 2);
                bf2[ni][0] = to_tf32(Bs[r * LDSP + col]);
                bf2[ni][1] = to_tf32(Bs[r * LDSP + col + 4]);
            }
            #pragma unroll
            for (int mi = 0; mi < 4; ++mi)
                #pragma unroll
                for (int ni = 0; ni < 4; ++ni)
                    mma_tf32(acc[mi][ni], af[mi], bf2[ni]);
        }
        rs = (rs + 1) % STAGES;
    }

    // epilogue: write raw gate pre-activations to scratch
    #pragma unroll
    for (int mi = 0; mi < 4; ++mi) {
        const int r0 = m0 + wm * 64 + mi * 16 + (lane >> 2);
        #pragma unroll
        for (int ni = 0; ni < 4; ++ni) {
            const int cg = n0 + wn * 32 + ni * 8 + (lane & 3) * 2;
            *(float2*)(g_gates + (size_t)r0 * N_SZ + cg) =
                make_float2(acc[mi][ni][0], acc[mi][ni][1]);
            *(float2*)(g_gates + (size_t)(r0 + 8) * N_SZ + cg) =
                make_float2(acc[mi][ni][2], acc[mi][ni][3]);
        }
    }
}

// ---------------- kernel 2: LSTM pointwise epilogue ----------------
DEVI float fsig(float x) {
    float e = __expf(-x);
    float r;
    asm("rcp.approx.f32 %0, %1;" : "=f"(r) : "f"(1.0f + e));
    return r;
}
DEVI float ftanh_(float x) { return fmaf(2.0f, fsig(2.0f * x), -1.0f); }

DEVI void lstm_elem(float fp, float ip, float gp, float op, float cp,
                    float& h, float& c) {
    float f = fsig(fp), i = fsig(ip), g = ftanh_(gp), o = fsig(op);
    c = fmaf(f, cp, i * g);
    h = o * ftanh_(c);
}

__global__ void __launch_bounds__(256)
lstm_pointwise_kernel(const float* __restrict__ c_prev,
                      const float* __restrict__ bf, const float* __restrict__ bi,
                      const float* __restrict__ bg, const float* __restrict__ bo,
                      float* __restrict__ out)
{
    const size_t idx = (size_t)blockIdx.x * 256 + threadIdx.x;  // vec4 over B*H
    const int m  = (int)(idx >> 9);            // / (H/4 = 512)
    const int h4 = ((int)idx & 511) * 4;

    const float* grow = g_gates + (size_t)m * N_SZ;
    float4 fv = *(const float4*)(grow + h4);
    float4 iv = *(const float4*)(grow + H_SZ + h4);
    float4 gv = *(const float4*)(grow + 2 * H_SZ + h4);
    float4 ov = *(const float4*)(grow + 3 * H_SZ + h4);
    float4 cb = *(const float4*)(c_prev + (size_t)m * H_SZ + h4);
    float4 vbf = *(const float4*)(bf + h4);
    float4 vbi = *(const float4*)(bi + h4);
    float4 vbg = *(const float4*)(bg + h4);
    float4 vbo = *(const float4*)(bo + h4);

    float4 hv, cv;
    lstm_elem(fv.x + vbf.x, iv.x + vbi.x, gv.x + vbg.x, ov.x + vbo.x, cb.x, hv.x, cv.x);
    lstm_elem(fv.y + vbf.y, iv.y + vbi.y, gv.y + vbg.y, ov.y + vbo.y, cb.y, hv.y, cv.y);
    lstm_elem(fv.z + vbf.z, iv.z + vbi.z, gv.z + vbg.z, ov.z + vbo.z, cb.z, hv.z, cv.z);
    lstm_elem(fv.w + vbf.w, iv.w + vbi.w, gv.w + vbg.w, ov.w + vbo.w, cb.w, hv.w, cv.w);

    *(float4*)(out + (size_t)m * H_SZ + h4) = hv;
    *(float4*)(out + (size_t)B_SZ * H_SZ + (size_t)m * H_SZ + h4) = cv;
}

// ---------------- host side ----------------
extern "C" void kernel_launch(void* const* d_in, const int* in_sizes, int n_in,
                              void* d_out, int out_size) {
    (void)in_sizes; (void)n_in; (void)out_size;
    // inputs: 0 input, 1 h_prev, 2 c_prev, 3 Wf, 4 bf, 5 Wi, 6 bi, 7 Wg, 8 bg, 9 Wo, 10 bo
    const float* inp = (const float*)d_in[0];
    const float* hpv = (const float*)d_in[1];
    const float* cpv = (const float*)d_in[2];
    const float* Wf  = (const float*)d_in[3];
    const float* bf  = (const float*)d_in[4];
    const float* Wi  = (const float*)d_in[5];
    const float* bi  = (const float*)d_in[6];
    const float* Wg  = (const float*)d_in[7];
    const float* bg  = (const float*)d_in[8];
    const float* Wo  = (const float*)d_in[9];
    const float* bo  = (const float*)d_in[10];
    float* out = (float*)d_out;

    cudaFuncSetAttribute(gemm_gates_kernel,
                         cudaFuncAttributeMaxDynamicSharedMemorySize, SMEM_BYTES);

    const int grid1 = (B_SZ / BM) * (N_SZ / BN);        // 4096
    gemm_gates_kernel<<<grid1, 256, SMEM_BYTES>>>(inp, hpv, Wf, Wi, Wg, Wo);

    const int grid2 = (B_SZ * H_SZ / 4) / 256;          // 16384
    lstm_pointwise_kernel<<<grid2, 256>>>(cpv, bf, bi, bg, bo, out);
}

// round 3
// speedup vs baseline: 1.0893x; 1.0893x over previous
#include <cuda_runtime.h>
#include <cstdint>
#include <cstddef>

// ---------------- problem constants ----------------
constexpr int B_SZ  = 8192;
constexpr int IN_SZ = 2048;
constexpr int H_SZ  = 2048;
constexpr int K_SZ  = IN_SZ + H_SZ;       // 4096
constexpr int N_SZ  = 4 * H_SZ;           // 8192 (f,i,g,o stacked)

// GEMM tiling
constexpr int BM = 128, BN = 128, BK = 32;
constexpr int STAGES = 3;
constexpr int KT = K_SZ / BK;             // 128 k-tiles
constexpr int LDSP = 36;                  // padded floats per smem row
constexpr int TILE_F = 128 * LDSP;
constexpr int SMEM_BYTES = 2 * STAGES * TILE_F * 4;   // 110592 B

// static device scratch (sanctioned path — no allocations)
__device__ float g_gates[(size_t)B_SZ * N_SZ];          // 268 MB
__device__ float g_Acat [(size_t)B_SZ * K_SZ];          // 134 MB, tf32-rounded [B,4096]
__device__ float g_Wcat [(size_t)N_SZ * K_SZ];          // 134 MB, tf32-rounded [8192,4096]

#define DEVI __device__ __forceinline__

DEVI uint32_t smem_u32(const void* p) {
    uint32_t a;
    asm("{ .reg .u64 t; cvta.to.shared.u64 t, %1; cvt.u32.u64 %0, t; }"
        : "=r"(a) : "l"(p));
    return a;
}

DEVI void cp_async16(uint32_t dst, const void* src) {
    asm volatile("cp.async.cg.shared.global [%0], [%1], 16;"
                 :: "r"(dst), "l"(src) : "memory");
}
DEVI void cp_commit() { asm volatile("cp.async.commit_group;" ::: "memory"); }
template <int N> DEVI void cp_wait() {
    asm volatile("cp.async.wait_group %0;" :: "n"(N) : "memory");
}

DEVI float round_tf32(float x) {
    float y;
    asm("cvt.rna.tf32.f32 %0, %1;" : "=f"(y) : "f"(x));
    return y;
}

DEVI void mma_tf32(float c[4], const uint32_t a[4], const uint32_t b[2]) {
    asm volatile(
        "mma.sync.aligned.m16n8k8.row.col.f32.tf32.tf32.f32 "
        "{%0,%1,%2,%3},{%4,%5,%6,%7},{%8,%9},{%0,%1,%2,%3};"
        : "+f"(c[0]), "+f"(c[1]), "+f"(c[2]), "+f"(c[3])
        : "r"(a[0]), "r"(a[1]), "r"(a[2]), "r"(a[3]), "r"(b[0]), "r"(b[1]));
}

// ---------------- prepass: concat + round-to-tf32 ----------------
__global__ void __launch_bounds__(256)
prep_A_kernel(const float* __restrict__ inp, const float* __restrict__ hpv) {
    const size_t idx = (size_t)blockIdx.x * 256 + threadIdx.x;  // vec4 over [B,4096]
    const int row  = (int)(idx >> 10);            // / 1024 vec4 per row
    const int col4 = ((int)idx & 1023) * 4;
    const float* src = (col4 < IN_SZ) ? (inp + (size_t)row * IN_SZ + col4)
                                      : (hpv + (size_t)row * H_SZ + (col4 - IN_SZ));
    float4 v = *(const float4*)src;
    v.x = round_tf32(v.x); v.y = round_tf32(v.y);
    v.z = round_tf32(v.z); v.w = round_tf32(v.w);
    *(float4*)(g_Acat + (size_t)row * K_SZ + col4) = v;
}

__global__ void __launch_bounds__(256)
prep_W_kernel(const float* __restrict__ Wf, const float* __restrict__ Wi,
              const float* __restrict__ Wg, const float* __restrict__ Wo) {
    const size_t idx = (size_t)blockIdx.x * 256 + threadIdx.x;  // vec4 over [8192,4096]
    const int row  = (int)(idx >> 10);
    const int col4 = ((int)idx & 1023) * 4;
    const int gate = row >> 11;                    // /2048
    const int r    = row & 2047;
    const float* W = (gate == 0) ? Wf : (gate == 1) ? Wi : (gate == 2) ? Wg : Wo;
    float4 v = *(const float4*)(W + (size_t)r * K_SZ + col4);
    v.x = round_tf32(v.x); v.y = round_tf32(v.y);
    v.z = round_tf32(v.z); v.w = round_tf32(v.w);
    *(float4*)(g_Wcat + (size_t)row * K_SZ + col4) = v;
}

// ---------------- kernel 1: fused 4-gate GEMM (pre-rounded tf32) ----------------
__global__ void __launch_bounds__(256, 2)
gemm_gates_kernel()
{
    extern __shared__ float sm[];
    float* smA = sm;                       // [STAGES][128][36]
    float* smB = sm + STAGES * TILE_F;

    const int tid  = threadIdx.x;
    const int lane = tid & 31;
    const int warp = tid >> 5;
    const int wm   = warp >> 2;            // 0..1  (M)
    const int wn   = warp & 3;             // 0..3  (N)

    // grid swizzle: 8 m-tiles per group for L2 reuse; adjacent bids share nt
    constexpr int NT = N_SZ / BN;           // 64
    constexpr int GM = 8;
    const int bid   = blockIdx.x;
    const int group = bid / (GM * NT);
    const int rem   = bid % (GM * NT);
    const int mt    = group * GM + (rem % GM);
    const int nt    = rem / GM;

    const int m0 = mt * BM;
    const int n0 = nt * BN;

    const uint32_t smA_u = smem_u32(smA);
    const uint32_t smB_u = smem_u32(smB);

    auto load_stage = [&](int kt, int st) {
        const int kb = kt * BK;
        const uint32_t adst = smA_u + st * TILE_F * 4;
        const uint32_t bdst = smB_u + st * TILE_F * 4;
        #pragma unroll
        for (int i = 0; i < 4; ++i) {
            const int lin = tid + i * 256;          // 0..1023
            const int row = lin >> 3;               // 0..127
            const int c4  = (lin & 7) * 4;          // 0..28
            cp_async16(adst + (row * LDSP + c4) * 4,
                       g_Acat + (size_t)(m0 + row) * K_SZ + kb + c4);
            cp_async16(bdst + (row * LDSP + c4) * 4,
                       g_Wcat + (size_t)(n0 + row) * K_SZ + kb + c4);
        }
    };

    float acc[4][4][4];
    #pragma unroll
    for (int a = 0; a < 4; ++a)
        #pragma unroll
        for (int b = 0; b < 4; ++b)
            #pragma unroll
            for (int c = 0; c < 4; ++c) acc[a][b][c] = 0.f;

    load_stage(0, 0); cp_commit();
    load_stage(1, 1); cp_commit();

    int rs = 0;
    for (int kt = 0; kt < KT; ++kt) {
        cp_wait<STAGES - 2>();
        __syncthreads();

        if (kt + STAGES - 1 < KT) load_stage(kt + STAGES - 1, (kt + STAGES - 1) % STAGES);
        cp_commit();

        const float* As = smA + rs * TILE_F;
        const float* Bs = smB + rs * TILE_F;

        #pragma unroll
        for (int ks = 0; ks < 4; ++ks) {
            const int col = ks * 8 + (lane & 3);
            uint32_t af[4][4], bf2[4][2];
            #pragma unroll
            for (int mi = 0; mi < 4; ++mi) {
                const int r = wm * 64 + mi * 16 + (lane >> 2);
                af[mi][0] = __float_as_uint(As[r * LDSP + col]);
                af[mi][1] = __float_as_uint(As[(r + 8) * LDSP + col]);
                af[mi][2] = __float_as_uint(As[r * LDSP + col + 4]);
                af[mi][3] = __float_as_uint(As[(r + 8) * LDSP + col + 4]);
            }
            #pragma unroll
            for (int ni = 0; ni < 4; ++ni) {
                const int r = wn * 32 + ni * 8 + (lane >> 2);
                bf2[ni][0] = __float_as_uint(Bs[r * LDSP + col]);
                bf2[ni][1] = __float_as_uint(Bs[r * LDSP + col + 4]);
            }
            #pragma unroll
            for (int mi = 0; mi < 4; ++mi)
                #pragma unroll
                for (int ni = 0; ni < 4; ++ni)
                    mma_tf32(acc[mi][ni], af[mi], bf2[ni]);
        }
        rs = (rs + 1) % STAGES;
    }

    #pragma unroll
    for (int mi = 0; mi < 4; ++mi) {
        const int r0 = m0 + wm * 64 + mi * 16 + (lane >> 2);
        #pragma unroll
        for (int ni = 0; ni < 4; ++ni) {
            const int cg = n0 + wn * 32 + ni * 8 + (lane & 3) * 2;
            *(float2*)(g_gates + (size_t)r0 * N_SZ + cg) =
                make_float2(acc[mi][ni][0], acc[mi][ni][1]);
            *(float2*)(g_gates + (size_t)(r0 + 8) * N_SZ + cg) =
                make_float2(acc[mi][ni][2], acc[mi][ni][3]);
        }
    }
}

// ---------------- kernel 2: LSTM pointwise epilogue ----------------
DEVI float fsig(float x) {
    float e = __expf(-x);
    float r;
    asm("rcp.approx.f32 %0, %1;" : "=f"(r) : "f"(1.0f + e));
    return r;
}
DEVI float ftanh_(float x) { return fmaf(2.0f, fsig(2.0f * x), -1.0f); }

DEVI void lstm_elem(float fp, float ip, float gp, float op, float cp,
                    float& h, float& c) {
    float f = fsig(fp), i = fsig(ip), g = ftanh_(gp), o = fsig(op);
    c = fmaf(f, cp, i * g);
    h = o * ftanh_(c);
}

__global__ void __launch_bounds__(256)
lstm_pointwise_kernel(const float* __restrict__ c_prev,
                      const float* __restrict__ bf, const float* __restrict__ bi,
                      const float* __restrict__ bg, const float* __restrict__ bo,
                      float* __restrict__ out)
{
    const size_t idx = (size_t)blockIdx.x * 256 + threadIdx.x;
    const int m  = (int)(idx >> 9);
    const int h4 = ((int)idx & 511) * 4;

    const float* grow = g_gates + (size_t)m * N_SZ;
    float4 fv = *(const float4*)(grow + h4);
    float4 iv = *(const float4*)(grow + H_SZ + h4);
    float4 gv = *(const float4*)(grow + 2 * H_SZ + h4);
    float4 ov = *(const float4*)(grow + 3 * H_SZ + h4);
    float4 cb = *(const float4*)(c_prev + (size_t)m * H_SZ + h4);
    float4 vbf = *(const float4*)(bf + h4);
    float4 vbi = *(const float4*)(bi + h4);
    float4 vbg = *(const float4*)(bg + h4);
    float4 vbo = *(const float4*)(bo + h4);

    float4 hv, cv;
    lstm_elem(fv.x + vbf.x, iv.x + vbi.x, gv.x + vbg.x, ov.x + vbo.x, cb.x, hv.x, cv.x);
    lstm_elem(fv.y + vbf.y, iv.y + vbi.y, gv.y + vbg.y, ov.y + vbo.y, cb.y, hv.y, cv.y);
    lstm_elem(fv.z + vbf.z, iv.z + vbi.z, gv.z + vbg.z, ov.z + vbo.z, cb.z, hv.z, cv.z);
    lstm_elem(fv.w + vbf.w, iv.w + vbi.w, gv.w + vbg.w, ov.w + vbo.w, cb.w, hv.w, cv.w);

    *(float4*)(out + (size_t)m * H_SZ + h4) = hv;
    *(float4*)(out + (size_t)B_SZ * H_SZ + (size_t)m * H_SZ + h4) = cv;
}

// ---------------- host side ----------------
extern "C" void kernel_launch(void* const* d_in, const int* in_sizes, int n_in,
                              void* d_out, int out_size) {
    (void)in_sizes; (void)n_in; (void)out_size;
    const float* inp = (const float*)d_in[0];
    const float* hpv = (const float*)d_in[1];
    const float* cpv = (const float*)d_in[2];
    const float* Wf  = (const float*)d_in[3];
    const float* bf  = (const float*)d_in[4];
    const float* Wi  = (const float*)d_in[5];
    const float* bi  = (const float*)d_in[6];
    const float* Wg  = (const float*)d_in[7];
    const float* bg  = (const float*)d_in[8];
    const float* Wo  = (const float*)d_in[9];
    const float* bo  = (const float*)d_in[10];
    float* out = (float*)d_out;

    // prepass: round inputs/weights to tf32 once (removes cvts from GEMM mainloop)
    const int gridA = (int)(((size_t)B_SZ * K_SZ / 4) / 256);   // 32768
    prep_A_kernel<<<gridA, 256>>>(inp, hpv);
    const int gridW = (int)(((size_t)N_SZ * K_SZ / 4) / 256);   // 32768
    prep_W_kernel<<<gridW, 256>>>(Wf, Wi, Wg, Wo);

    cudaFuncSetAttribute(gemm_gates_kernel,
                         cudaFuncAttributeMaxDynamicSharedMemorySize, SMEM_BYTES);

    const int grid1 = (B_SZ / BM) * (N_SZ / BN);        // 4096
    gemm_gates_kernel<<<grid1, 256, SMEM_BYTES>>>();

    const int grid2 = (B_SZ * H_SZ / 4) / 256;          // 16384
    lstm_pointwise_kernel<<<grid2, 256>>>(cpv, bf, bi, bg, bo, out);
}

// round 4
// speedup vs baseline: 2.3115x; 2.1221x over previous
#include <cuda_runtime.h>
#include <cuda_fp16.h>
#include <cstdint>
#include <cstddef>

// ---------------- problem constants ----------------
constexpr int B_SZ  = 8192;
constexpr int IN_SZ = 2048;
constexpr int H_SZ  = 2048;
constexpr int K_SZ  = IN_SZ + H_SZ;       // 4096
constexpr int N_SZ  = 4 * H_SZ;           // 8192 (f,i,g,o stacked)

// GEMM tiling (fp16 path)
constexpr int BM = 128, BN = 128, BK = 64;
constexpr int STAGES = 3;
constexpr int KT = K_SZ / BK;             // 64 k-tiles
constexpr int LDSP2 = 72;                 // padded fp16 per smem row (144B, conflict-free)
constexpr int STAGE_H_BYTES = 128 * LDSP2 * 2;        // 18432 B per operand tile
constexpr int SMEM_BYTES = 2 * STAGES * STAGE_H_BYTES; // 110592 B

// static device scratch
__device__ float  g_gates[(size_t)B_SZ * N_SZ];        // 268 MB fp32 pre-activations
__device__ __half g_Ah[(size_t)B_SZ * K_SZ];           // 67 MB fp16 concat(input, h_prev)
__device__ __half g_Wh[(size_t)N_SZ * K_SZ];           // 67 MB fp16 concat(Wf,Wi,Wg,Wo)

#define DEVI __device__ __forceinline__

DEVI uint32_t smem_u32(const void* p) {
    uint32_t a;
    asm("{ .reg .u64 t; cvta.to.shared.u64 t, %1; cvt.u32.u64 %0, t; }"
        : "=r"(a) : "l"(p));
    return a;
}

DEVI void cp_async16(uint32_t dst, const void* src) {
    asm volatile("cp.async.cg.shared.global [%0], [%1], 16;"
                 :: "r"(dst), "l"(src) : "memory");
}
DEVI void cp_commit() { asm volatile("cp.async.commit_group;" ::: "memory"); }
template <int N> DEVI void cp_wait() {
    asm volatile("cp.async.wait_group %0;" :: "n"(N) : "memory");
}

DEVI void ldsm_x4(uint32_t r[4], uint32_t addr) {
    asm volatile("ldmatrix.sync.aligned.m8n8.x4.shared.b16 {%0,%1,%2,%3}, [%4];"
                 : "=r"(r[0]), "=r"(r[1]), "=r"(r[2]), "=r"(r[3]) : "r"(addr));
}

DEVI void mma_f16(float c[4], const uint32_t a[4], const uint32_t b0, const uint32_t b1) {
    asm volatile(
        "mma.sync.aligned.m16n8k16.row.col.f32.f16.f16.f32 "
        "{%0,%1,%2,%3},{%4,%5,%6,%7},{%8,%9},{%0,%1,%2,%3};"
        : "+f"(c[0]), "+f"(c[1]), "+f"(c[2]), "+f"(c[3])
        : "r"(a[0]), "r"(a[1]), "r"(a[2]), "r"(a[3]), "r"(b0), "r"(b1));
}

// ---------------- prepass: concat + convert to fp16 ----------------
// 8 elements (16B fp16) per thread
__global__ void __launch_bounds__(256)
prep_A_kernel(const float* __restrict__ inp, const float* __restrict__ hpv) {
    const size_t idx = (size_t)blockIdx.x * 256 + threadIdx.x;  // vec8 over [B,4096]
    const int row  = (int)(idx >> 9);             // 512 vec8 per row
    const int col8 = ((int)idx & 511) * 8;
    const float* src = (col8 < IN_SZ) ? (inp + (size_t)row * IN_SZ + col8)
                                      : (hpv + (size_t)row * H_SZ + (col8 - IN_SZ));
    float4 v0 = *(const float4*)src;
    float4 v1 = *(const float4*)(src + 4);
    __half2 h[4];
    h[0] = __floats2half2_rn(v0.x, v0.y);
    h[1] = __floats2half2_rn(v0.z, v0.w);
    h[2] = __floats2half2_rn(v1.x, v1.y);
    h[3] = __floats2half2_rn(v1.z, v1.w);
    *(uint4*)(g_Ah + (size_t)row * K_SZ + col8) = *(const uint4*)h;
}

__global__ void __launch_bounds__(256)
prep_W_kernel(const float* __restrict__ Wf, const float* __restrict__ Wi,
              const float* __restrict__ Wg, const float* __restrict__ Wo) {
    const size_t idx = (size_t)blockIdx.x * 256 + threadIdx.x;  // vec8 over [8192,4096]
    const int row  = (int)(idx >> 9);
    const int col8 = ((int)idx & 511) * 8;
    const int gate = row >> 11;
    const int r    = row & 2047;
    const float* W = (gate == 0) ? Wf : (gate == 1) ? Wi : (gate == 2) ? Wg : Wo;
    const float* src = W + (size_t)r * K_SZ + col8;
    float4 v0 = *(const float4*)src;
    float4 v1 = *(const float4*)(src + 4);
    __half2 h[4];
    h[0] = __floats2half2_rn(v0.x, v0.y);
    h[1] = __floats2half2_rn(v0.z, v0.w);
    h[2] = __floats2half2_rn(v1.x, v1.y);
    h[3] = __floats2half2_rn(v1.z, v1.w);
    *(uint4*)(g_Wh + (size_t)row * K_SZ + col8) = *(const uint4*)h;
}

// ---------------- kernel 1: fused 4-gate fp16 GEMM ----------------
__global__ void __launch_bounds__(256, 2)
gemm_gates_kernel()
{
    extern __shared__ __half smh[];
    const uint32_t smA_u = smem_u32(smh);
    const uint32_t smB_u = smA_u + STAGES * STAGE_H_BYTES;

    const int tid  = threadIdx.x;
    const int lane = tid & 31;
    const int warp = tid >> 5;
    const int wm   = warp >> 2;            // 0..1  (M)
    const int wn   = warp & 3;             // 0..3  (N)

    // grid swizzle: 8 m-tiles per group; adjacent bids share n-tile
    constexpr int NT = N_SZ / BN;           // 64
    constexpr int GM = 8;
    const int bid   = blockIdx.x;
    const int group = bid / (GM * NT);
    const int rem   = bid % (GM * NT);
    const int mt    = group * GM + (rem % GM);
    const int nt    = rem / GM;
    const int m0 = mt * BM;
    const int n0 = nt * BN;

    // ---- stage loader: 128 rows x 128 bytes per operand ----
    auto load_stage = [&](int kt, int st) {
        const int kb = kt * BK;
        const uint32_t adst = smA_u + st * STAGE_H_BYTES;
        const uint32_t bdst = smB_u + st * STAGE_H_BYTES;
        #pragma unroll
        for (int i = 0; i < 4; ++i) {
            const int lin = tid + i * 256;          // 0..1023
            const int row = lin >> 3;               // 0..127
            const int c8  = (lin & 7) * 8;          // fp16 col: 0,8,...,56
            cp_async16(adst + row * (LDSP2 * 2) + c8 * 2,
                       g_Ah + (size_t)(m0 + row) * K_SZ + kb + c8);
            cp_async16(bdst + row * (LDSP2 * 2) + c8 * 2,
                       g_Wh + (size_t)(n0 + row) * K_SZ + kb + c8);
        }
    };

    float acc[4][4][4];
    #pragma unroll
    for (int a = 0; a < 4; ++a)
        #pragma unroll
        for (int b = 0; b < 4; ++b)
            #pragma unroll
            for (int c = 0; c < 4; ++c) acc[a][b][c] = 0.f;

    load_stage(0, 0); cp_commit();
    load_stage(1, 1); cp_commit();

    // per-thread ldmatrix row/col selectors (in fp16 elements)
    const int a_row = (lane & 15);                 // + base row
    const int a_col = (lane >> 4) * 8;             // 0 or 8 within k16 slice
    const int b_row = (lane & 7) + (lane >> 4) * 8; // within 16-row n-pair
    const int b_col = ((lane >> 3) & 1) * 8;       // 0 or 8 within k16 slice

    int rs = 0;
    for (int kt = 0; kt < KT; ++kt) {
        cp_wait<STAGES - 2>();
        __syncthreads();

        if (kt + STAGES - 1 < KT) load_stage(kt + STAGES - 1, (kt + STAGES - 1) % STAGES);
        cp_commit();

        const uint32_t As = smA_u + rs * STAGE_H_BYTES;
        const uint32_t Bs = smB_u + rs * STAGE_H_BYTES;

        #pragma unroll
        for (int ks = 0; ks < 4; ++ks) {            // 4 x k16
            const int k0 = ks * 16;
            uint32_t af[4][4], bf[2][4];
            #pragma unroll
            for (int mi = 0; mi < 4; ++mi) {
                const int r = wm * 64 + mi * 16 + a_row;
                ldsm_x4(af[mi], As + (r * LDSP2 + k0 + a_col) * 2);
            }
            #pragma unroll
            for (int np = 0; np < 2; ++np) {        // n-pairs: covers ni = 2np, 2np+1
                const int r = wn * 32 + np * 16 + b_row;
                ldsm_x4(bf[np], Bs + (r * LDSP2 + k0 + b_col) * 2);
            }
            #pragma unroll
            for (int mi = 0; mi < 4; ++mi) {
                #pragma unroll
                for (int np = 0; np < 2; ++np) {
                    mma_f16(acc[mi][2 * np + 0], af[mi], bf[np][0], bf[np][1]);
                    mma_f16(acc[mi][2 * np + 1], af[mi], bf[np][2], bf[np][3]);
                }
            }
        }
        rs = (rs + 1) % STAGES;
    }

    // epilogue: raw pre-activations to scratch
    #pragma unroll
    for (int mi = 0; mi < 4; ++mi) {
        const int r0 = m0 + wm * 64 + mi * 16 + (lane >> 2);
        #pragma unroll
        for (int ni = 0; ni < 4; ++ni) {
            const int cg = n0 + wn * 32 + ni * 8 + (lane & 3) * 2;
            *(float2*)(g_gates + (size_t)r0 * N_SZ + cg) =
                make_float2(acc[mi][ni][0], acc[mi][ni][1]);
            *(float2*)(g_gates + (size_t)(r0 + 8) * N_SZ + cg) =
                make_float2(acc[mi][ni][2], acc[mi][ni][3]);
        }
    }
}

// ---------------- kernel 2: LSTM pointwise epilogue ----------------
DEVI float fsig(float x) {
    float e = __expf(-x);
    float r;
    asm("rcp.approx.f32 %0, %1;" : "=f"(r) : "f"(1.0f + e));
    return r;
}
DEVI float ftanh_(float x) { return fmaf(2.0f, fsig(2.0f * x), -1.0f); }

DEVI void lstm_elem(float fp, float ip, float gp, float op, float cp,
                    float& h, float& c) {
    float f = fsig(fp), i = fsig(ip), g = ftanh_(gp), o = fsig(op);
    c = fmaf(f, cp, i * g);
    h = o * ftanh_(c);
}

__global__ void __launch_bounds__(256)
lstm_pointwise_kernel(const float* __restrict__ c_prev,
                      const float* __restrict__ bf, const float* __restrict__ bi,
                      const float* __restrict__ bg, const float* __restrict__ bo,
                      float* __restrict__ out)
{
    const size_t idx = (size_t)blockIdx.x * 256 + threadIdx.x;
    const int m  = (int)(idx >> 9);
    const int h4 = ((int)idx & 511) * 4;

    const float* grow = g_gates + (size_t)m * N_SZ;
    float4 fv = *(const float4*)(grow + h4);
    float4 iv = *(const float4*)(grow + H_SZ + h4);
    float4 gv = *(const float4*)(grow + 2 * H_SZ + h4);
    float4 ov = *(const float4*)(grow + 3 * H_SZ + h4);
    float4 cb = *(const float4*)(c_prev + (size_t)m * H_SZ + h4);
    float4 vbf = *(const float4*)(bf + h4);
    float4 vbi = *(const float4*)(bi + h4);
    float4 vbg = *(const float4*)(bg + h4);
    float4 vbo = *(const float4*)(bo + h4);

    float4 hv, cv;
    lstm_elem(fv.x + vbf.x, iv.x + vbi.x, gv.x + vbg.x, ov.x + vbo.x, cb.x, hv.x, cv.x);
    lstm_elem(fv.y + vbf.y, iv.y + vbi.y, gv.y + vbg.y, ov.y + vbo.y, cb.y, hv.y, cv.y);
    lstm_elem(fv.z + vbf.z, iv.z + vbi.z, gv.z + vbg.z, ov.z + vbo.z, cb.z, hv.z, cv.z);
    lstm_elem(fv.w + vbf.w, iv.w + vbi.w, gv.w + vbg.w, ov.w + vbo.w, cb.w, hv.w, cv.w);

    *(float4*)(out + (size_t)m * H_SZ + h4) = hv;
    *(float4*)(out + (size_t)B_SZ * H_SZ + (size_t)m * H_SZ + h4) = cv;
}

// ---------------- host side ----------------
extern "C" void kernel_launch(void* const* d_in, const int* in_sizes, int n_in,
                              void* d_out, int out_size) {
    (void)in_sizes; (void)n_in; (void)out_size;
    const float* inp = (const float*)d_in[0];
    const float* hpv = (const float*)d_in[1];
    const float* cpv = (const float*)d_in[2];
    const float* Wf  = (const float*)d_in[3];
    const float* bf  = (const float*)d_in[4];
    const float* Wi  = (const float*)d_in[5];
    const float* bi  = (const float*)d_in[6];
    const float* Wg  = (const float*)d_in[7];
    const float* bg  = (const float*)d_in[8];
    const float* Wo  = (const float*)d_in[9];
    const float* bo  = (const float*)d_in[10];
    float* out = (float*)d_out;

    // prepass: concat + fp16 conversion (once; removes all in-loop cvts)
    const int gridA = (int)(((size_t)B_SZ * K_SZ / 8) / 256);   // 16384
    prep_A_kernel<<<gridA, 256>>>(inp, hpv);
    const int gridW = (int)(((size_t)N_SZ * K_SZ / 8) / 256);   // 16384
    prep_W_kernel<<<gridW, 256>>>(Wf, Wi, Wg, Wo);

    cudaFuncSetAttribute(gemm_gates_kernel,
                         cudaFuncAttributeMaxDynamicSharedMemorySize, SMEM_BYTES);

    const int grid1 = (B_SZ / BM) * (N_SZ / BN);        // 4096
    gemm_gates_kernel<<<grid1, 256, SMEM_BYTES>>>();

    const int grid2 = (B_SZ * H_SZ / 4) / 256;          // 16384
    lstm_pointwise_kernel<<<grid2, 256>>>(cpv, bf, bi, bg, bo, out);
}